// round 16
// baseline (speedup 1.0000x reference)
#include <cuda_runtime.h>
#include <cuda_fp16.h>
#include <cstdint>

#define BB 8
#define TT 4096
#define EE 1024
#define HH 64

// fp16-packed projected tensors, fragment-ready layouts:
// g_q16/g_k16: [B*T][32 words]; word w of a row holds heads (2w',2w'+1); within
//   each 8-word group the word order is permuted (w,w+4) -> adjacent.
//   g_q16 additionally carries the softmax scale: q' = q * 0.125 * log2(e).
// g_v16: [B][64 heads][T/2 key-pair words], same per-8-group permutation.
// g_w16: [192 n-rows (k|q|v heads)][512 k-pair words], permuted.
__device__ uint32_t g_q16[BB * TT * 32];
__device__ uint32_t g_k16[BB * TT * 32];
__device__ uint32_t g_v16[BB * 64 * (TT / 2)];
__device__ uint32_t g_w16[192 * 512];
__device__ float    g_l[BB * TT];   // softmax denominators (atomic accum)

// ---------------------------------------------------------------------------
static __device__ __forceinline__ uint32_t smem_u32(const void* p) {
    uint32_t a;
    asm("{ .reg .u64 t; cvta.to.shared.u64 t, %1; cvt.u32.u64 %0, t; }"
        : "=r"(a) : "l"(p));
    return a;
}
// pack two fp32 -> fp16x2 (lo = first arg)
static __device__ __forceinline__ uint32_t ph2(float lo, float hi) {
    uint32_t d;
    asm("cvt.rn.f16x2.f32 %0, %1, %2;" : "=r"(d) : "f"(hi), "f"(lo));
    return d;
}
// packed fp16x2 2^x
static __device__ __forceinline__ uint32_t ex2h2(uint32_t x) {
    uint32_t y;
    asm("ex2.approx.f16x2 %0, %1;" : "=r"(y) : "r"(x));
    return y;
}
// packed fp16x2 add (fma/alu pipe — keeps l-sum off the tensor pipe)
static __device__ __forceinline__ uint32_t h2add(uint32_t a, uint32_t b) {
    uint32_t y;
    asm("add.f16x2 %0, %1, %2;" : "=r"(y) : "r"(a), "r"(b));
    return y;
}
// D += A * B, m16n8k16 fp16 with fp32 accum
static __device__ __forceinline__ void mma16(float* d, const uint32_t* a,
                                             const uint32_t* b) {
    asm volatile(
        "mma.sync.aligned.m16n8k16.row.col.f32.f16.f16.f32 "
        "{%0,%1,%2,%3}, {%4,%5,%6,%7}, {%8,%9}, {%0,%1,%2,%3};"
        : "+f"(d[0]), "+f"(d[1]), "+f"(d[2]), "+f"(d[3])
        : "r"(a[0]), "r"(a[1]), "r"(a[2]), "r"(a[3]), "r"(b[0]), "r"(b[1]));
}
static __device__ __forceinline__ void cpa16(uint32_t s, const void* g) {
    asm volatile("cp.async.cg.shared.global [%0], [%1], 16;"
                 :: "r"(s), "l"(g) : "memory");
}
#define CPA_COMMIT() asm volatile("cp.async.commit_group;" ::: "memory")
#define CPA_WAIT(n)  asm volatile("cp.async.wait_group %0;" :: "n"(n) : "memory")

static __device__ __forceinline__ int perm8(int u) {
    return (u < 4) ? 2 * u : 2 * u - 7;
}

// ---------------------------------------------------------------------------
// conv_w: pack W^T into g_w16 [192 rows][512 words], permuted pair layout.
// ---------------------------------------------------------------------------
__global__ __launch_bounds__(256) void conv_w_kernel(
    const float* __restrict__ Wk,
    const float* __restrict__ Wq,
    const float* __restrict__ Wv)
{
    __shared__ float tile[128 * 65];
    const int mat  = blockIdx.x >> 3;       // 0..2
    const int slab = blockIdx.x & 7;        // 128-row k slab
    const float* Wsel = (mat == 0) ? Wk : ((mat == 1) ? Wq : Wv);
    const int tid = threadIdx.x;

    #pragma unroll
    for (int it = 0; it < 8; it++) {
        int p = tid + it * 256;
        int row = p >> 4, c4 = p & 15;
        float4 v = *reinterpret_cast<const float4*>(
            &Wsel[(size_t)(slab * 128 + row) * HH + c4 * 4]);
        float* d = &tile[row * 65 + c4 * 4];
        d[0] = v.x; d[1] = v.y; d[2] = v.z; d[3] = v.w;
    }
    __syncthreads();

    #pragma unroll
    for (int it = 0; it < 16; it++) {
        int id = tid + it * 256;
        int wl = id & 63;                    // local w-pair
        int h  = id >> 6;                    // 0..63
        int w  = slab * 64 + wl;
        uint32_t word = ph2(tile[(2 * wl) * 65 + h], tile[(2 * wl + 1) * 65 + h]);
        int pos = (w & ~7) | perm8(w & 7);
        g_w16[(size_t)(mat * 64 + h) * 512 + pos] = word;
    }
}

// ---------------------------------------------------------------------------
// Normalize: out[b,t,:] /= g_l[b,t]. 4 float4 per thread (deeper MLP).
// ---------------------------------------------------------------------------
__global__ void norm_kernel(float* __restrict__ out) {
    int base = blockIdx.x * 1024 + threadIdx.x;
    #pragma unroll
    for (int it = 0; it < 4; it++) {
        int i = base + it * 256;                     // float4 index
        float inv = 1.0f / g_l[i >> 4];              // 16 float4 per row
        float4 v = reinterpret_cast<float4*>(out)[i];
        v.x *= inv; v.y *= inv; v.z *= inv; v.w *= inv;
        reinterpret_cast<float4*>(out)[i] = v;
    }
}

// ---------------------------------------------------------------------------
// Projection (R11 config): [x@Wk | x@Wq | x@Wv], fp16 mma m16n8k16 mainloop.
// 512 threads, block tile M=128 x N=192, 256 blocks. Double-buffered smem,
// ONE __syncthreads per k-chunk. Zero-fills out + g_l at start.
// Epilogue folds the softmax scale (0.125*log2 e) into g_q16.
// smem: 2 x (xs [128][40] | ws [192][40]) = 102400 B.
// ---------------------------------------------------------------------------
#define PST 40
#define PBUF (128 * PST + 192 * PST)
#define PROJ_SMEM (2 * PBUF * 4)

__global__ __launch_bounds__(512) void proj_kernel(
    const float* __restrict__ x,
    float* __restrict__ out)
{
    extern __shared__ uint32_t sm[];

    const int tid  = threadIdx.x;
    const int lane = tid & 31;
    const int wid  = tid >> 5;
    const int gID  = lane >> 2;
    const int tig  = lane & 3;
    const int wm   = wid & 3;
    const int wn   = wid >> 2;
    const int m0   = blockIdx.x * 128;

    // Zero-fill out + g_l (grid: 256 blocks * 512 thr = 131072)
    {
        int gtid = blockIdx.x * 512 + tid;
        float4 z = make_float4(0.f, 0.f, 0.f, 0.f);
        #pragma unroll
        for (int i = 0; i < 4; i++)
            reinterpret_cast<float4*>(out)[gtid + i * 131072] = z;
        if (gtid < (BB * TT) / 4)
            reinterpret_cast<float4*>(g_l)[gtid] = z;
    }

    float4 xr[4];
    uint4  wr[3];

    #pragma unroll
    for (int it = 0; it < 4; it++) {
        int p = tid + it * 512;
        xr[it] = *reinterpret_cast<const float4*>(
            &x[(size_t)(m0 + (p >> 4)) * EE + (p & 15) * 4]);
    }
    #pragma unroll
    for (int it = 0; it < 3; it++) {
        int p = tid + it * 512;
        wr[it] = reinterpret_cast<const uint4*>(g_w16)[(p >> 3) * 128 + (p & 7)];
    }

    float acc[2][6][4];
    #pragma unroll
    for (int mt = 0; mt < 2; mt++)
        #pragma unroll
        for (int j = 0; j < 6; j++)
            #pragma unroll
            for (int c = 0; c < 4; c++) acc[mt][j][c] = 0.0f;

    for (int kc = 0; kc < 16; kc++) {
        uint32_t* xs = sm + (kc & 1) * PBUF;             // [128][40]
        uint32_t* ws = xs + 128 * PST;                   // [192][40]

        // Store prefetched regs -> smem (x packed to fp16 pairs, permuted).
        // Buffer kc&1 was last read by mma(kc-2), which precedes the barrier
        // of iteration kc-1 in every warp -> safe without a second barrier.
        #pragma unroll
        for (int it = 0; it < 4; it++) {
            int p = tid + it * 512;
            int row = p >> 4, c4 = p & 15;
            int g  = c4 >> 2;
            int u  = (2 * c4) & 7;            // even
            int p0 = g * 8 + perm8(u);
            int p1 = g * 8 + perm8(u + 1);
            xs[row * PST + p0] = ph2(xr[it].x, xr[it].y);
            xs[row * PST + p1] = ph2(xr[it].z, xr[it].w);
        }
        #pragma unroll
        for (int it = 0; it < 3; it++) {
            int p = tid + it * 512;
            *reinterpret_cast<uint4*>(&ws[(p >> 3) * PST + (p & 7) * 4]) = wr[it];
        }
        __syncthreads();   // tiles of chunk kc visible to all warps

        if (kc < 15) {
            const int k0n = (kc + 1) * 64;
            #pragma unroll
            for (int it = 0; it < 4; it++) {
                int p = tid + it * 512;
                xr[it] = *reinterpret_cast<const float4*>(
                    &x[(size_t)(m0 + (p >> 4)) * EE + k0n + (p & 15) * 4]);
            }
            #pragma unroll
            for (int it = 0; it < 3; it++) {
                int p = tid + it * 512;
                wr[it] = reinterpret_cast<const uint4*>(
                    g_w16)[(p >> 3) * 128 + (kc + 1) * 8 + (p & 7)];
            }
        }

        #pragma unroll
        for (int kk = 0; kk < 4; kk++) {
            uint32_t aF[2][4];
            #pragma unroll
            for (int mt = 0; mt < 2; mt++) {
                int r = wm * 32 + mt * 16;
                uint2 a0 = *reinterpret_cast<const uint2*>(
                    &xs[(r + gID) * PST + kk * 8 + 2 * tig]);
                uint2 a1 = *reinterpret_cast<const uint2*>(
                    &xs[(r + gID + 8) * PST + kk * 8 + 2 * tig]);
                aF[mt][0] = a0.x; aF[mt][1] = a1.x;
                aF[mt][2] = a0.y; aF[mt][3] = a1.y;
            }
            #pragma unroll
            for (int j = 0; j < 6; j++) {
                int n = wn * 48 + j * 8 + gID;
                uint2 b = *reinterpret_cast<const uint2*>(
                    &ws[n * PST + kk * 8 + 2 * tig]);
                uint32_t bF[2] = {b.x, b.y};
                mma16(acc[0][j], aF[0], bF);
                mma16(acc[1][j], aF[1], bF);
            }
        }
    }

    // Epilogue -> packed fp16 fragment-ready layouts.
    // q columns (64..127) are pre-scaled by 0.125*log2(e) so attention's
    // softmax needs no per-element multiply.
    const float QSCL = 0.125f * 1.44269504088896f;
    #pragma unroll
    for (int mt = 0; mt < 2; mt++) {
        #pragma unroll
        for (int j = 0; j < 6; j++) {
            const int col = wn * 48 + j * 8 + 2 * tig;   // even
            const int r0  = m0 + wm * 32 + mt * 16 + gID;
            if (col < 128) {
                const float s = (col >= 64) ? QSCL : 1.0f;
                uint32_t wlo = ph2(acc[mt][j][0] * s, acc[mt][j][1] * s);
                uint32_t whi = ph2(acc[mt][j][2] * s, acc[mt][j][3] * s);
                int wd  = (col & 63) >> 1;
                int pos = (wd & ~7) | perm8(wd & 7);
                uint32_t* base = (col < 64) ? g_k16 : g_q16;
                base[(size_t)r0 * 32 + pos]        = wlo;
                base[(size_t)(r0 + 8) * 32 + pos]  = whi;
            } else {
                float p0 = __shfl_down_sync(0xffffffffu, acc[mt][j][0], 4);
                float p1 = __shfl_down_sync(0xffffffffu, acc[mt][j][1], 4);
                float p2 = __shfl_down_sync(0xffffffffu, acc[mt][j][2], 4);
                float p3 = __shfl_down_sync(0xffffffffu, acc[mt][j][3], 4);
                if (!(gID & 1)) {
                    int c   = col - 128;
                    int bb  = r0 / TT;
                    int t   = r0 % TT;          // even
                    int kp0 = t >> 1, kp1 = (t + 8) >> 1;
                    int vp0 = (kp0 & ~7) | perm8(kp0 & 7);
                    int vp1 = (kp1 & ~7) | perm8(kp1 & 7);
                    size_t vb  = ((size_t)bb * 64 + c) * (TT / 2);
                    size_t vb1 = vb + (TT / 2);
                    g_v16[vb  + vp0] = ph2(acc[mt][j][0], p0);
                    g_v16[vb1 + vp0] = ph2(acc[mt][j][1], p1);
                    g_v16[vb  + vp1] = ph2(acc[mt][j][2], p2);
                    g_v16[vb1 + vp1] = ph2(acc[mt][j][3], p3);
                }
            }
        }
    }
}

// ---------------------------------------------------------------------------
// Attention (causal, split-KV, fp16 mma, register-resident P, h2 exp,
// register-hoisted Q fragments, l via HADD2 TREE on the fma/alu pipe).
// R15 structure otherwise: 3-stage K/V cp.async ring, ONE __syncthreads per
// tile, no per-j branching. The l ones-mma (4 mma/tile on the saturated
// tensor pipe) is replaced by 14 add.f16x2 + converts on idle pipes; the
// per-lane partial sums are shuffle-reduced once at the end.
// smem: Qs 128x40 | K[3] 64x40 | V[3] 64x40 = 81920 B (2 CTAs/SM).
// ---------------------------------------------------------------------------
#define AST 40
#define ATTN_SMEM ((128 * AST + 6 * 64 * AST) * 4)   // 81920

static __device__ __forceinline__ void attn_issue_kv(
    int b, int k0, int tid, uint32_t Ka, uint32_t Va)
{
    const uint32_t* kp = g_k16 + ((size_t)(b * TT + k0)) * 32;
    const uint32_t* vp = g_v16 + (size_t)b * 64 * (TT / 2) + (k0 >> 1);
    #pragma unroll
    for (int it = 0; it < 2; it++) {
        int p = tid + it * 256;
        int r = p >> 3, c4 = p & 7;
        cpa16(Ka + (uint32_t)(r * AST + c4 * 4) * 4, kp + (size_t)r * 32 + c4 * 4);
        cpa16(Va + (uint32_t)(r * AST + c4 * 4) * 4,
              vp + (size_t)r * (TT / 2) + c4 * 4);
    }
}

__global__ __launch_bounds__(256, 2) void attn_kernel(float* __restrict__ out)
{
    extern __shared__ uint32_t sm[];
    uint32_t* Qs = sm;                            // [128][40]
    const uint32_t sb = smem_u32(sm);
    const uint32_t Qa = sb;
    uint32_t* Ksb[3];
    uint32_t* Vsb[3];
    uint32_t Kaa[3], Vaa[3];
    #pragma unroll
    for (int i = 0; i < 3; i++) {
        Ksb[i] = sm + (128 + i * 64) * AST;
        Vsb[i] = sm + (128 + 192 + i * 64) * AST;
        Kaa[i] = sb + (uint32_t)(128 + i * 64) * AST * 4;
        Vaa[i] = sb + (uint32_t)(128 + 192 + i * 64) * AST * 4;
    }

    const int tid  = threadIdx.x;
    const int lane = tid & 31;
    const int wid  = tid >> 5;
    const int gID  = lane >> 2;
    const int tig  = lane & 3;

    // Block -> (b, qt, chunk); heavy q-tiles first, even chunk sizes.
    const int b = blockIdx.x & 7;
    const int r = blockIdx.x >> 3;            // 0..79
    int qt = 0, ch = 0;
    {
        int acc = 0;
        for (int q = 31; q >= 0; q--) {
            int n = (q >> 3) + 1;
            if (r < acc + n) { qt = q; ch = r - acc; break; }
            acc += n;
        }
    }
    const int q0   = qt * 128;
    const int ntot = 2 * (qt + 1);
    const int nch  = (qt >> 3) + 1;
    const int kt_beg = ch * ntot / nch;
    const int kt_end = (ch + 1) * ntot / nch;
    const int qrow   = wid * 16;

    // Prologue: group 0 = Q tile + KV(kt_beg); group 1 = KV(kt_beg+1)
    const uint32_t* qp = g_q16 + ((size_t)(b * TT + q0)) * 32;
    #pragma unroll
    for (int it = 0; it < 4; it++) {
        int p = tid + it * 256;
        int rr = p >> 3, c4 = p & 7;
        cpa16(Qa + (uint32_t)(rr * AST + c4 * 4) * 4,
              qp + (size_t)rr * 32 + c4 * 4);
    }
    attn_issue_kv(b, kt_beg * 64, tid, Kaa[0], Vaa[0]);
    CPA_COMMIT();
    if (kt_beg + 1 < kt_end)
        attn_issue_kv(b, (kt_beg + 1) * 64, tid, Kaa[1], Vaa[1]);
    CPA_COMMIT();

    // Hoist Q fragments: group 0 landed after WAIT(1); visible after barrier.
    CPA_WAIT(1);
    __syncthreads();
    uint32_t qF[4][4];
    #pragma unroll
    for (int kk = 0; kk < 4; kk++) {
        uint2 qv0 = *reinterpret_cast<const uint2*>(
            &Qs[(qrow + gID) * AST + kk * 8 + 2 * tig]);
        uint2 qv1 = *reinterpret_cast<const uint2*>(
            &Qs[(qrow + gID + 8) * AST + kk * 8 + 2 * tig]);
        qF[kk][0] = qv0.x; qF[kk][1] = qv1.x;
        qF[kk][2] = qv0.y; qF[kk][3] = qv1.y;
    }

    float oacc[8][4];
    #pragma unroll
    for (int j = 0; j < 8; j++)
        #pragma unroll
        for (int c = 0; c < 4; c++) oacc[j][c] = 0.0f;
    float lp0 = 0.0f, lp1 = 0.0f;   // per-lane partial l sums (16 keys each)

    int d = 0;  // ring index of current tile
    for (int kt = kt_beg; kt < kt_end; kt++) {
        const int k0 = kt * 64;

        CPA_WAIT(1);       // tile kt's group landed (kt+1's may be in flight)
        __syncthreads();   // all warps: see tile kt; done reading tile kt-1

        // Issue tile kt+2 into buffer (d+2)%3 (== tile kt-1's buffer, free).
        int d2 = d + 2; if (d2 >= 3) d2 -= 3;
        if (kt + 2 < kt_end)
            attn_issue_kv(b, (kt + 2) * 64, tid, Kaa[d2], Vaa[d2]);
        CPA_COMMIT();      // empty group near the tail keeps counts aligned

        uint32_t* Ks = Ksb[d];
        uint32_t* Vs = Vsb[d];

        // S = Q K^T : warp tile 16 x 64, 4 k16 chunks (Q from registers)
        float sacc[8][4];
        #pragma unroll
        for (int j = 0; j < 8; j++)
            #pragma unroll
            for (int c = 0; c < 4; c++) sacc[j][c] = 0.0f;

        #pragma unroll
        for (int kk = 0; kk < 4; kk++) {
            #pragma unroll
            for (int j = 0; j < 8; j++) {
                uint2 kb = *reinterpret_cast<const uint2*>(
                    &Ks[(j * 8 + gID) * AST + kk * 8 + 2 * tig]);
                uint32_t bF[2] = {kb.x, kb.y};
                mma16(sacc[j], qF[kk], bF);
            }
        }

        // Softmax: causal mask (diag tiles only) + pack + one ex2.f16x2 per
        // pair -> packed fp16 P fragment word directly. No scale FMULs.
        const bool masked = (kt >= 2 * qt);
        const int row0 = q0 + qrow + gID;
        const int row1 = row0 + 8;
        uint32_t pF[4][4];
        #pragma unroll
        for (int j = 0; j < 8; j++) {
            int col = k0 + j * 8 + 2 * tig;
            float a00 = sacc[j][0];
            float a01 = sacc[j][1];
            float a10 = sacc[j][2];
            float a11 = sacc[j][3];
            if (masked) {
                if (col     > row0) a00 = -1e4f;
                if (col + 1 > row0) a01 = -1e4f;
                if (col     > row1) a10 = -1e4f;
                if (col + 1 > row1) a11 = -1e4f;
            }
            pF[j >> 1][(j & 1) * 2]     = ex2h2(ph2(a00, a01));
            pF[j >> 1][(j & 1) * 2 + 1] = ex2h2(ph2(a10, a11));
        }

        // l partial sums via HADD2 tree (fma/alu pipe; tensor pipe untouched).
        // Row0 words: pF[kk][0], pF[kk][2]; row1 words: pF[kk][1], pF[kk][3].
        {
            uint32_t s0 = h2add(h2add(h2add(pF[0][0], pF[0][2]),
                                      h2add(pF[1][0], pF[1][2])),
                                h2add(h2add(pF[2][0], pF[2][2]),
                                      h2add(pF[3][0], pF[3][2])));
            uint32_t s1 = h2add(h2add(h2add(pF[0][1], pF[0][3]),
                                      h2add(pF[1][1], pF[1][3])),
                                h2add(h2add(pF[2][1], pF[2][3]),
                                      h2add(pF[3][1], pF[3][3])));
            float2 f0 = __half22float2(*reinterpret_cast<__half2*>(&s0));
            float2 f1 = __half22float2(*reinterpret_cast<__half2*>(&s1));
            lp0 += f0.x + f0.y;
            lp1 += f1.x + f1.y;
        }

        // O += P V : P straight from registers
        #pragma unroll
        for (int kk = 0; kk < 4; kk++) {
            #pragma unroll
            for (int j = 0; j < 8; j++) {
                uint2 vb = *reinterpret_cast<const uint2*>(
                    &Vs[(j * 8 + gID) * AST + kk * 8 + 2 * tig]);
                uint32_t bF[2] = {vb.x, vb.y};
                mma16(oacc[j], pF[kk], bF);
            }
        }

        if (++d == 3) d = 0;
    }

    // Partial-result combine: atomicAdd O and l
    const int row0g = b * TT + q0 + qrow + gID;
    float* o0 = out + (size_t)row0g * HH;
    float* o1 = o0 + 8 * HH;
    #pragma unroll
    for (int j = 0; j < 8; j++) {
        int c = j * 8 + 2 * tig;
        atomicAdd(o0 + c,     oacc[j][0]);
        atomicAdd(o0 + c + 1, oacc[j][1]);
        atomicAdd(o1 + c,     oacc[j][2]);
        atomicAdd(o1 + c + 1, oacc[j][3]);
    }
    // Reduce l partials across the 4 tig lanes of each row group.
    lp0 += __shfl_xor_sync(0xffffffffu, lp0, 1);
    lp0 += __shfl_xor_sync(0xffffffffu, lp0, 2);
    lp1 += __shfl_xor_sync(0xffffffffu, lp1, 1);
    lp1 += __shfl_xor_sync(0xffffffffu, lp1, 2);
    if (tig == 0) {
        atomicAdd(&g_l[row0g],     lp0);
        atomicAdd(&g_l[row0g + 8], lp1);
    }
}

// ---------------------------------------------------------------------------
extern "C" void kernel_launch(void* const* d_in, const int* in_sizes, int n_in,
                              void* d_out, int out_size)
{
    const float* x  = (const float*)d_in[0];
    const float* Wk = (const float*)d_in[1];
    const float* Wq = (const float*)d_in[2];
    const float* Wv = (const float*)d_in[3];
    float* out = (float*)d_out;
    (void)in_sizes; (void)n_in; (void)out_size;

    cudaFuncSetAttribute(proj_kernel,
                         cudaFuncAttributeMaxDynamicSharedMemorySize, PROJ_SMEM);
    cudaFuncSetAttribute(attn_kernel,
                         cudaFuncAttributeMaxDynamicSharedMemorySize, ATTN_SMEM);

    conv_w_kernel<<<24, 256>>>(Wk, Wq, Wv);
    proj_kernel<<<BB * TT / 128, 512, PROJ_SMEM>>>(x, out);
    attn_kernel<<<640, 256, ATTN_SMEM>>>(out);
    norm_kernel<<<512, 256>>>(out);
}

// round 17
// speedup vs baseline: 1.0124x; 1.0124x over previous
#include <cuda_runtime.h>
#include <cuda_fp16.h>
#include <cstdint>

#define BB 8
#define TT 4096
#define EE 1024
#define HH 64

// fp16-packed projected tensors, fragment-ready layouts:
// g_q16/g_k16: [B*T][32 words]; word w of a row holds heads (2w',2w'+1); within
//   each 8-word group the word order is permuted (w,w+4) -> adjacent.
//   g_q16 additionally carries the softmax scale: q' = q * 0.125 * log2(e).
// g_v16: [B][64 heads][T/2 key-pair words], same per-8-group permutation.
// g_w16: [192 n-rows (k|q|v heads)][512 k-pair words], permuted.
__device__ uint32_t g_q16[BB * TT * 32];
__device__ uint32_t g_k16[BB * TT * 32];
__device__ uint32_t g_v16[BB * 64 * (TT / 2)];
__device__ uint32_t g_w16[192 * 512];
__device__ float    g_l[BB * TT];   // softmax denominators (atomic accum)

// ---------------------------------------------------------------------------
static __device__ __forceinline__ uint32_t smem_u32(const void* p) {
    uint32_t a;
    asm("{ .reg .u64 t; cvta.to.shared.u64 t, %1; cvt.u32.u64 %0, t; }"
        : "=r"(a) : "l"(p));
    return a;
}
// pack two fp32 -> fp16x2 (lo = first arg)
static __device__ __forceinline__ uint32_t ph2(float lo, float hi) {
    uint32_t d;
    asm("cvt.rn.f16x2.f32 %0, %1, %2;" : "=r"(d) : "f"(hi), "f"(lo));
    return d;
}
// packed fp16x2 2^x
static __device__ __forceinline__ uint32_t ex2h2(uint32_t x) {
    uint32_t y;
    asm("ex2.approx.f16x2 %0, %1;" : "=r"(y) : "r"(x));
    return y;
}
// packed fp16x2 add (fma/alu pipe — keeps l-sum off the tensor pipe)
static __device__ __forceinline__ uint32_t h2add(uint32_t a, uint32_t b) {
    uint32_t y;
    asm("add.f16x2 %0, %1, %2;" : "=r"(y) : "r"(a), "r"(b));
    return y;
}
// D += A * B, m16n8k16 fp16 with fp32 accum
static __device__ __forceinline__ void mma16(float* d, const uint32_t* a,
                                             const uint32_t* b) {
    asm volatile(
        "mma.sync.aligned.m16n8k16.row.col.f32.f16.f16.f32 "
        "{%0,%1,%2,%3}, {%4,%5,%6,%7}, {%8,%9}, {%0,%1,%2,%3};"
        : "+f"(d[0]), "+f"(d[1]), "+f"(d[2]), "+f"(d[3])
        : "r"(a[0]), "r"(a[1]), "r"(a[2]), "r"(a[3]), "r"(b[0]), "r"(b[1]));
}
static __device__ __forceinline__ void cpa16(uint32_t s, const void* g) {
    asm volatile("cp.async.cg.shared.global [%0], [%1], 16;"
                 :: "r"(s), "l"(g) : "memory");
}
#define CPA_COMMIT() asm volatile("cp.async.commit_group;" ::: "memory")
#define CPA_WAIT(n)  asm volatile("cp.async.wait_group %0;" :: "n"(n) : "memory")

static __device__ __forceinline__ int perm8(int u) {
    return (u < 4) ? 2 * u : 2 * u - 7;
}

// ---------------------------------------------------------------------------
// conv_w: pack W^T into g_w16 [192 rows][512 words], permuted pair layout.
// ---------------------------------------------------------------------------
__global__ __launch_bounds__(256) void conv_w_kernel(
    const float* __restrict__ Wk,
    const float* __restrict__ Wq,
    const float* __restrict__ Wv)
{
    __shared__ float tile[128 * 65];
    const int mat  = blockIdx.x >> 3;       // 0..2
    const int slab = blockIdx.x & 7;        // 128-row k slab
    const float* Wsel = (mat == 0) ? Wk : ((mat == 1) ? Wq : Wv);
    const int tid = threadIdx.x;

    #pragma unroll
    for (int it = 0; it < 8; it++) {
        int p = tid + it * 256;
        int row = p >> 4, c4 = p & 15;
        float4 v = *reinterpret_cast<const float4*>(
            &Wsel[(size_t)(slab * 128 + row) * HH + c4 * 4]);
        float* d = &tile[row * 65 + c4 * 4];
        d[0] = v.x; d[1] = v.y; d[2] = v.z; d[3] = v.w;
    }
    __syncthreads();

    #pragma unroll
    for (int it = 0; it < 16; it++) {
        int id = tid + it * 256;
        int wl = id & 63;                    // local w-pair
        int h  = id >> 6;                    // 0..63
        int w  = slab * 64 + wl;
        uint32_t word = ph2(tile[(2 * wl) * 65 + h], tile[(2 * wl + 1) * 65 + h]);
        int pos = (w & ~7) | perm8(w & 7);
        g_w16[(size_t)(mat * 64 + h) * 512 + pos] = word;
    }
}

// ---------------------------------------------------------------------------
// Normalize rows t in [1024, 4096) of each batch (rows < 1024 are normalized
// in-place by their single attn chunk block). 96 blocks per batch.
// ---------------------------------------------------------------------------
__global__ void norm_kernel(float* __restrict__ out) {
    const int b    = blockIdx.x / 96;
    const int rem  = blockIdx.x % 96;
    const int base = rem * 512 + threadIdx.x;    // f4 index in kept region
    #pragma unroll
    for (int it = 0; it < 2; it++) {
        int i   = base + it * 256;               // 0..49151
        int t   = 1024 + (i >> 4);
        float inv = 1.0f / g_l[b * TT + t];
        float4* op = reinterpret_cast<float4*>(out)
                   + ((size_t)(b * TT + t) * 16) + (i & 15);
        float4 v = *op;
        v.x *= inv; v.y *= inv; v.z *= inv; v.w *= inv;
        *op = v;
    }
}

// ---------------------------------------------------------------------------
// Projection (R11 config): [x@Wk | x@Wq | x@Wv], fp16 mma m16n8k16 mainloop.
// 512 threads, block tile M=128 x N=192, 256 blocks. Double-buffered smem,
// ONE __syncthreads per k-chunk. Zero-fills out + g_l at start.
// Epilogue folds the softmax scale (0.125*log2 e) into g_q16.
// smem: 2 x (xs [128][40] | ws [192][40]) = 102400 B.
// ---------------------------------------------------------------------------
#define PST 40
#define PBUF (128 * PST + 192 * PST)
#define PROJ_SMEM (2 * PBUF * 4)

__global__ __launch_bounds__(512) void proj_kernel(
    const float* __restrict__ x,
    float* __restrict__ out)
{
    extern __shared__ uint32_t sm[];

    const int tid  = threadIdx.x;
    const int lane = tid & 31;
    const int wid  = tid >> 5;
    const int gID  = lane >> 2;
    const int tig  = lane & 3;
    const int wm   = wid & 3;
    const int wn   = wid >> 2;
    const int m0   = blockIdx.x * 128;

    // Zero-fill out + g_l (grid: 256 blocks * 512 thr = 131072)
    {
        int gtid = blockIdx.x * 512 + tid;
        float4 z = make_float4(0.f, 0.f, 0.f, 0.f);
        #pragma unroll
        for (int i = 0; i < 4; i++)
            reinterpret_cast<float4*>(out)[gtid + i * 131072] = z;
        if (gtid < (BB * TT) / 4)
            reinterpret_cast<float4*>(g_l)[gtid] = z;
    }

    float4 xr[4];
    uint4  wr[3];

    #pragma unroll
    for (int it = 0; it < 4; it++) {
        int p = tid + it * 512;
        xr[it] = *reinterpret_cast<const float4*>(
            &x[(size_t)(m0 + (p >> 4)) * EE + (p & 15) * 4]);
    }
    #pragma unroll
    for (int it = 0; it < 3; it++) {
        int p = tid + it * 512;
        wr[it] = reinterpret_cast<const uint4*>(g_w16)[(p >> 3) * 128 + (p & 7)];
    }

    float acc[2][6][4];
    #pragma unroll
    for (int mt = 0; mt < 2; mt++)
        #pragma unroll
        for (int j = 0; j < 6; j++)
            #pragma unroll
            for (int c = 0; c < 4; c++) acc[mt][j][c] = 0.0f;

    for (int kc = 0; kc < 16; kc++) {
        uint32_t* xs = sm + (kc & 1) * PBUF;             // [128][40]
        uint32_t* ws = xs + 128 * PST;                   // [192][40]

        // Store prefetched regs -> smem (x packed to fp16 pairs, permuted).
        #pragma unroll
        for (int it = 0; it < 4; it++) {
            int p = tid + it * 512;
            int row = p >> 4, c4 = p & 15;
            int g  = c4 >> 2;
            int u  = (2 * c4) & 7;            // even
            int p0 = g * 8 + perm8(u);
            int p1 = g * 8 + perm8(u + 1);
            xs[row * PST + p0] = ph2(xr[it].x, xr[it].y);
            xs[row * PST + p1] = ph2(xr[it].z, xr[it].w);
        }
        #pragma unroll
        for (int it = 0; it < 3; it++) {
            int p = tid + it * 512;
            *reinterpret_cast<uint4*>(&ws[(p >> 3) * PST + (p & 7) * 4]) = wr[it];
        }
        __syncthreads();   // tiles of chunk kc visible to all warps

        if (kc < 15) {
            const int k0n = (kc + 1) * 64;
            #pragma unroll
            for (int it = 0; it < 4; it++) {
                int p = tid + it * 512;
                xr[it] = *reinterpret_cast<const float4*>(
                    &x[(size_t)(m0 + (p >> 4)) * EE + k0n + (p & 15) * 4]);
            }
            #pragma unroll
            for (int it = 0; it < 3; it++) {
                int p = tid + it * 512;
                wr[it] = reinterpret_cast<const uint4*>(
                    g_w16)[(p >> 3) * 128 + (kc + 1) * 8 + (p & 7)];
            }
        }

        #pragma unroll
        for (int kk = 0; kk < 4; kk++) {
            uint32_t aF[2][4];
            #pragma unroll
            for (int mt = 0; mt < 2; mt++) {
                int r = wm * 32 + mt * 16;
                uint2 a0 = *reinterpret_cast<const uint2*>(
                    &xs[(r + gID) * PST + kk * 8 + 2 * tig]);
                uint2 a1 = *reinterpret_cast<const uint2*>(
                    &xs[(r + gID + 8) * PST + kk * 8 + 2 * tig]);
                aF[mt][0] = a0.x; aF[mt][1] = a1.x;
                aF[mt][2] = a0.y; aF[mt][3] = a1.y;
            }
            #pragma unroll
            for (int j = 0; j < 6; j++) {
                int n = wn * 48 + j * 8 + gID;
                uint2 b = *reinterpret_cast<const uint2*>(
                    &ws[n * PST + kk * 8 + 2 * tig]);
                uint32_t bF[2] = {b.x, b.y};
                mma16(acc[0][j], aF[0], bF);
                mma16(acc[1][j], aF[1], bF);
            }
        }
    }

    // Epilogue -> packed fp16 fragment-ready layouts.
    const float QSCL = 0.125f * 1.44269504088896f;
    #pragma unroll
    for (int mt = 0; mt < 2; mt++) {
        #pragma unroll
        for (int j = 0; j < 6; j++) {
            const int col = wn * 48 + j * 8 + 2 * tig;   // even
            const int r0  = m0 + wm * 32 + mt * 16 + gID;
            if (col < 128) {
                const float s = (col >= 64) ? QSCL : 1.0f;
                uint32_t wlo = ph2(acc[mt][j][0] * s, acc[mt][j][1] * s);
                uint32_t whi = ph2(acc[mt][j][2] * s, acc[mt][j][3] * s);
                int wd  = (col & 63) >> 1;
                int pos = (wd & ~7) | perm8(wd & 7);
                uint32_t* base = (col < 64) ? g_k16 : g_q16;
                base[(size_t)r0 * 32 + pos]        = wlo;
                base[(size_t)(r0 + 8) * 32 + pos]  = whi;
            } else {
                float p0 = __shfl_down_sync(0xffffffffu, acc[mt][j][0], 4);
                float p1 = __shfl_down_sync(0xffffffffu, acc[mt][j][1], 4);
                float p2 = __shfl_down_sync(0xffffffffu, acc[mt][j][2], 4);
                float p3 = __shfl_down_sync(0xffffffffu, acc[mt][j][3], 4);
                if (!(gID & 1)) {
                    int c   = col - 128;
                    int bb  = r0 / TT;
                    int t   = r0 % TT;          // even
                    int kp0 = t >> 1, kp1 = (t + 8) >> 1;
                    int vp0 = (kp0 & ~7) | perm8(kp0 & 7);
                    int vp1 = (kp1 & ~7) | perm8(kp1 & 7);
                    size_t vb  = ((size_t)bb * 64 + c) * (TT / 2);
                    size_t vb1 = vb + (TT / 2);
                    g_v16[vb  + vp0] = ph2(acc[mt][j][0], p0);
                    g_v16[vb1 + vp0] = ph2(acc[mt][j][1], p1);
                    g_v16[vb  + vp1] = ph2(acc[mt][j][2], p2);
                    g_v16[vb1 + vp1] = ph2(acc[mt][j][3], p3);
                }
            }
        }
    }
}

// ---------------------------------------------------------------------------
// Attention (causal, split-KV, fp16 mma, register-resident P, h2 exp,
// register-hoisted Q fragments, l via HADD2 tree). Single-chunk q-tiles
// (nch==1, qt<8) normalize locally and write with plain stores; multi-chunk
// tiles combine via atomicAdd + separate norm kernel.
// 3-stage K/V cp.async ring, ONE __syncthreads per tile.
// smem: Qs 128x40 | K[3] 64x40 | V[3] 64x40 = 81920 B (2 CTAs/SM).
// ---------------------------------------------------------------------------
#define AST 40
#define ATTN_SMEM ((128 * AST + 6 * 64 * AST) * 4)   // 81920

static __device__ __forceinline__ void attn_issue_kv(
    int b, int k0, int tid, uint32_t Ka, uint32_t Va)
{
    const uint32_t* kp = g_k16 + ((size_t)(b * TT + k0)) * 32;
    const uint32_t* vp = g_v16 + (size_t)b * 64 * (TT / 2) + (k0 >> 1);
    #pragma unroll
    for (int it = 0; it < 2; it++) {
        int p = tid + it * 256;
        int r = p >> 3, c4 = p & 7;
        cpa16(Ka + (uint32_t)(r * AST + c4 * 4) * 4, kp + (size_t)r * 32 + c4 * 4);
        cpa16(Va + (uint32_t)(r * AST + c4 * 4) * 4,
              vp + (size_t)r * (TT / 2) + c4 * 4);
    }
}

__global__ __launch_bounds__(256, 2) void attn_kernel(float* __restrict__ out)
{
    extern __shared__ uint32_t sm[];
    uint32_t* Qs = sm;                            // [128][40]
    const uint32_t sb = smem_u32(sm);
    const uint32_t Qa = sb;
    uint32_t* Ksb[3];
    uint32_t* Vsb[3];
    uint32_t Kaa[3], Vaa[3];
    #pragma unroll
    for (int i = 0; i < 3; i++) {
        Ksb[i] = sm + (128 + i * 64) * AST;
        Vsb[i] = sm + (128 + 192 + i * 64) * AST;
        Kaa[i] = sb + (uint32_t)(128 + i * 64) * AST * 4;
        Vaa[i] = sb + (uint32_t)(128 + 192 + i * 64) * AST * 4;
    }

    const int tid  = threadIdx.x;
    const int lane = tid & 31;
    const int wid  = tid >> 5;
    const int gID  = lane >> 2;
    const int tig  = lane & 3;

    // Block -> (b, qt, chunk); heavy q-tiles first, even chunk sizes.
    const int b = blockIdx.x & 7;
    const int r = blockIdx.x >> 3;            // 0..79
    int qt = 0, ch = 0;
    {
        int acc = 0;
        for (int q = 31; q >= 0; q--) {
            int n = (q >> 3) + 1;
            if (r < acc + n) { qt = q; ch = r - acc; break; }
            acc += n;
        }
    }
    const int q0   = qt * 128;
    const int ntot = 2 * (qt + 1);
    const int nch  = (qt >> 3) + 1;
    const int kt_beg = ch * ntot / nch;
    const int kt_end = (ch + 1) * ntot / nch;
    const int qrow   = wid * 16;

    // Prologue: group 0 = Q tile + KV(kt_beg); group 1 = KV(kt_beg+1)
    const uint32_t* qp = g_q16 + ((size_t)(b * TT + q0)) * 32;
    #pragma unroll
    for (int it = 0; it < 4; it++) {
        int p = tid + it * 256;
        int rr = p >> 3, c4 = p & 7;
        cpa16(Qa + (uint32_t)(rr * AST + c4 * 4) * 4,
              qp + (size_t)rr * 32 + c4 * 4);
    }
    attn_issue_kv(b, kt_beg * 64, tid, Kaa[0], Vaa[0]);
    CPA_COMMIT();
    if (kt_beg + 1 < kt_end)
        attn_issue_kv(b, (kt_beg + 1) * 64, tid, Kaa[1], Vaa[1]);
    CPA_COMMIT();

    // Hoist Q fragments: group 0 landed after WAIT(1); visible after barrier.
    CPA_WAIT(1);
    __syncthreads();
    uint32_t qF[4][4];
    #pragma unroll
    for (int kk = 0; kk < 4; kk++) {
        uint2 qv0 = *reinterpret_cast<const uint2*>(
            &Qs[(qrow + gID) * AST + kk * 8 + 2 * tig]);
        uint2 qv1 = *reinterpret_cast<const uint2*>(
            &Qs[(qrow + gID + 8) * AST + kk * 8 + 2 * tig]);
        qF[kk][0] = qv0.x; qF[kk][1] = qv1.x;
        qF[kk][2] = qv0.y; qF[kk][3] = qv1.y;
    }

    float oacc[8][4];
    #pragma unroll
    for (int j = 0; j < 8; j++)
        #pragma unroll
        for (int c = 0; c < 4; c++) oacc[j][c] = 0.0f;
    float lp0 = 0.0f, lp1 = 0.0f;   // per-lane partial l sums (16 keys each)

    int d = 0;  // ring index of current tile
    for (int kt = kt_beg; kt < kt_end; kt++) {
        const int k0 = kt * 64;

        CPA_WAIT(1);       // tile kt's group landed (kt+1's may be in flight)
        __syncthreads();   // all warps: see tile kt; done reading tile kt-1

        // Issue tile kt+2 into buffer (d+2)%3 (== tile kt-1's buffer, free).
        int d2 = d + 2; if (d2 >= 3) d2 -= 3;
        if (kt + 2 < kt_end)
            attn_issue_kv(b, (kt + 2) * 64, tid, Kaa[d2], Vaa[d2]);
        CPA_COMMIT();      // empty group near the tail keeps counts aligned

        uint32_t* Ks = Ksb[d];
        uint32_t* Vs = Vsb[d];

        // S = Q K^T : warp tile 16 x 64, 4 k16 chunks (Q from registers)
        float sacc[8][4];
        #pragma unroll
        for (int j = 0; j < 8; j++)
            #pragma unroll
            for (int c = 0; c < 4; c++) sacc[j][c] = 0.0f;

        #pragma unroll
        for (int kk = 0; kk < 4; kk++) {
            #pragma unroll
            for (int j = 0; j < 8; j++) {
                uint2 kb = *reinterpret_cast<const uint2*>(
                    &Ks[(j * 8 + gID) * AST + kk * 8 + 2 * tig]);
                uint32_t bF[2] = {kb.x, kb.y};
                mma16(sacc[j], qF[kk], bF);
            }
        }

        // Softmax: causal mask (diag tiles only) + pack + one ex2.f16x2 per
        // pair -> packed fp16 P fragment word directly.
        const bool masked = (kt >= 2 * qt);
        const int row0 = q0 + qrow + gID;
        const int row1 = row0 + 8;
        uint32_t pF[4][4];
        #pragma unroll
        for (int j = 0; j < 8; j++) {
            int col = k0 + j * 8 + 2 * tig;
            float a00 = sacc[j][0];
            float a01 = sacc[j][1];
            float a10 = sacc[j][2];
            float a11 = sacc[j][3];
            if (masked) {
                if (col     > row0) a00 = -1e4f;
                if (col + 1 > row0) a01 = -1e4f;
                if (col     > row1) a10 = -1e4f;
                if (col + 1 > row1) a11 = -1e4f;
            }
            pF[j >> 1][(j & 1) * 2]     = ex2h2(ph2(a00, a01));
            pF[j >> 1][(j & 1) * 2 + 1] = ex2h2(ph2(a10, a11));
        }

        // l partial sums via HADD2 tree (fma/alu pipe; tensor pipe untouched).
        {
            uint32_t s0 = h2add(h2add(h2add(pF[0][0], pF[0][2]),
                                      h2add(pF[1][0], pF[1][2])),
                                h2add(h2add(pF[2][0], pF[2][2]),
                                      h2add(pF[3][0], pF[3][2])));
            uint32_t s1 = h2add(h2add(h2add(pF[0][1], pF[0][3]),
                                      h2add(pF[1][1], pF[1][3])),
                                h2add(h2add(pF[2][1], pF[2][3]),
                                      h2add(pF[3][1], pF[3][3])));
            float2 f0 = __half22float2(*reinterpret_cast<__half2*>(&s0));
            float2 f1 = __half22float2(*reinterpret_cast<__half2*>(&s1));
            lp0 += f0.x + f0.y;
            lp1 += f1.x + f1.y;
        }

        // O += P V : P straight from registers
        #pragma unroll
        for (int kk = 0; kk < 4; kk++) {
            #pragma unroll
            for (int j = 0; j < 8; j++) {
                uint2 vb = *reinterpret_cast<const uint2*>(
                    &Vs[(j * 8 + gID) * AST + kk * 8 + 2 * tig]);
                uint32_t bF[2] = {vb.x, vb.y};
                mma16(oacc[j], pF[kk], bF);
            }
        }

        if (++d == 3) d = 0;
    }

    // Reduce l partials across the 4 tig lanes (full sums in all lanes).
    lp0 += __shfl_xor_sync(0xffffffffu, lp0, 1);
    lp0 += __shfl_xor_sync(0xffffffffu, lp0, 2);
    lp1 += __shfl_xor_sync(0xffffffffu, lp1, 1);
    lp1 += __shfl_xor_sync(0xffffffffu, lp1, 2);

    const int row0g = b * TT + q0 + qrow + gID;
    float* o0 = out + (size_t)row0g * HH;
    float* o1 = o0 + 8 * HH;

    if (nch == 1) {
        // Sole contributor: normalize locally, plain stores, no g_l.
        const float inv0 = 1.0f / lp0;
        const float inv1 = 1.0f / lp1;
        #pragma unroll
        for (int j = 0; j < 8; j++) {
            int c = j * 8 + 2 * tig;
            *reinterpret_cast<float2*>(o0 + c) =
                make_float2(oacc[j][0] * inv0, oacc[j][1] * inv0);
            *reinterpret_cast<float2*>(o1 + c) =
                make_float2(oacc[j][2] * inv1, oacc[j][3] * inv1);
        }
    } else {
        #pragma unroll
        for (int j = 0; j < 8; j++) {
            int c = j * 8 + 2 * tig;
            atomicAdd(o0 + c,     oacc[j][0]);
            atomicAdd(o0 + c + 1, oacc[j][1]);
            atomicAdd(o1 + c,     oacc[j][2]);
            atomicAdd(o1 + c + 1, oacc[j][3]);
        }
        if (tig == 0) {
            atomicAdd(&g_l[row0g],     lp0);
            atomicAdd(&g_l[row0g + 8], lp1);
        }
    }
}

// ---------------------------------------------------------------------------
extern "C" void kernel_launch(void* const* d_in, const int* in_sizes, int n_in,
                              void* d_out, int out_size)
{
    const float* x  = (const float*)d_in[0];
    const float* Wk = (const float*)d_in[1];
    const float* Wq = (const float*)d_in[2];
    const float* Wv = (const float*)d_in[3];
    float* out = (float*)d_out;
    (void)in_sizes; (void)n_in; (void)out_size;

    cudaFuncSetAttribute(proj_kernel,
                         cudaFuncAttributeMaxDynamicSharedMemorySize, PROJ_SMEM);
    cudaFuncSetAttribute(attn_kernel,
                         cudaFuncAttributeMaxDynamicSharedMemorySize, ATTN_SMEM);

    conv_w_kernel<<<24, 256>>>(Wk, Wq, Wv);
    proj_kernel<<<BB * TT / 128, 512, PROJ_SMEM>>>(x, out);
    attn_kernel<<<640, 256, ATTN_SMEM>>>(out);
    norm_kernel<<<768, 256>>>(out);
}